// round 2
// baseline (speedup 1.0000x reference)
#include <cuda_runtime.h>
#include <cuda_bf16.h>
#include <math.h>

#define S_LEN 4096
#define HIDDEN 2048
#define NH 8
#define NKV 4
#define HD 256

// Scratch (allocation-free: device globals)
__device__ float g_q[(size_t)NH * S_LEN * HD];     // [h][s][d]
__device__ float g_k[(size_t)NKV * S_LEN * HD];    // [h][s][d]
__device__ float g_v[(size_t)NKV * S_LEN * HD];    // [h][s][d]
__device__ float g_attn[(size_t)S_LEN * (NH * HD)]; // [s][h*HD+d]

// ---------------------------------------------------------------------------
// Tiled fp32 SGEMM: C[M,N] = A[M,K] @ B[K,N]. 128x128 block tile, BK=8,
// 256 threads, 8x8 micro-tile with strided (ty+16i, tx+16j) mapping for
// conflict-free scalar LDS. headed=1 writes to [n>>8][m][n&255] layout.
// ---------------------------------------------------------------------------
__global__ __launch_bounds__(256) void sgemm_kernel(
    const float* __restrict__ A, const float* __restrict__ B,
    float* __restrict__ Cplain, float* __restrict__ Chead,
    int M, int N, int K, int headed)
{
    __shared__ float As[8 * 132];   // transposed, padded row stride 132
    __shared__ float Bs[8 * 128];

    const int tid = threadIdx.x;
    const int tx  = tid & 15;
    const int ty  = tid >> 4;
    const int bm  = blockIdx.y * 128;
    const int bn  = blockIdx.x * 128;

    const int am  = tid >> 1;        // 0..127 row of A tile
    const int ak  = (tid & 1) * 4;   // 0 or 4
    const int bk  = tid >> 5;        // 0..7 row of B tile
    const int bn4 = (tid & 31) * 4;  // col*4

    float acc[8][8];
#pragma unroll
    for (int i = 0; i < 8; i++)
#pragma unroll
        for (int j = 0; j < 8; j++) acc[i][j] = 0.f;

    for (int k0 = 0; k0 < K; k0 += 8) {
        float4 av = *(const float4*)&A[(size_t)(bm + am) * K + k0 + ak];
        float4 bv = *(const float4*)&B[(size_t)(k0 + bk) * N + bn + bn4];
        __syncthreads();
        As[(ak + 0) * 132 + am] = av.x;
        As[(ak + 1) * 132 + am] = av.y;
        As[(ak + 2) * 132 + am] = av.z;
        As[(ak + 3) * 132 + am] = av.w;
        *(float4*)&Bs[bk * 128 + bn4] = bv;
        __syncthreads();
#pragma unroll
        for (int kk = 0; kk < 8; kk++) {
            float a[8], b[8];
#pragma unroll
            for (int i = 0; i < 8; i++) a[i] = As[kk * 132 + ty + 16 * i];
#pragma unroll
            for (int j = 0; j < 8; j++) b[j] = Bs[kk * 128 + tx + 16 * j];
#pragma unroll
            for (int i = 0; i < 8; i++)
#pragma unroll
                for (int j = 0; j < 8; j++) acc[i][j] += a[i] * b[j];
        }
    }

    if (headed) {
#pragma unroll
        for (int i = 0; i < 8; i++) {
            int m = bm + ty + 16 * i;
#pragma unroll
            for (int j = 0; j < 8; j++) {
                int n = bn + tx + 16 * j;
                Chead[(size_t)(n >> 8) * ((size_t)M * HD) + (size_t)m * HD + (n & 255)] = acc[i][j];
            }
        }
    } else {
#pragma unroll
        for (int i = 0; i < 8; i++) {
            int m = bm + ty + 16 * i;
#pragma unroll
            for (int j = 0; j < 8; j++) {
                int n = bn + tx + 16 * j;
                Cplain[(size_t)m * N + n] = acc[i][j];
            }
        }
    }
}

// ---------------------------------------------------------------------------
// RoPE in-place on g_q and g_k. One thread per (head, seq, pair-index).
// position_ids may be int32 (JAX default, x64 disabled) or int64. Detect from
// the buffer: for arange(), 32-bit word[1] is 0 iff the data is int64.
// Phase range-reduced in double so sinf/cosf stay accurate under fast-math.
// ---------------------------------------------------------------------------
__global__ void rope_kernel(const void* __restrict__ pos_raw)
{
    int idx = blockIdx.x * blockDim.x + threadIdx.x;
    const int total = (NH + NKV) * S_LEN * (HD / 2);
    if (idx >= total) return;
    int i = idx & 127;                 // frequency index 0..127
    int s = (idx >> 7) & (S_LEN - 1);  // sequence position
    int h = idx >> 19;                 // 0..11: 0..7 -> q heads, 8..11 -> k heads

    const int* p32 = (const int*)pos_raw;
    long long pll = (p32[1] == 0) ? ((const long long*)pos_raw)[s]
                                  : (long long)p32[s];
    float p = (float)pll;

    // inv_freq = 10000^(-i/128)
    double invd = exp(-(double)i * (9.210340371976184 / 128.0));
    float f = (float)((double)p * invd);      // fp32 freq like reference
    const double TWO_PI = 6.283185307179586476925287;
    double r = (double)f;
    r -= TWO_PI * floor(r / TWO_PI);
    float sv = sinf((float)r);
    float cv = cosf((float)r);

    float* base = (h < NH) ? (g_q + ((size_t)h * S_LEN + s) * HD)
                           : (g_k + ((size_t)(h - NH) * S_LEN + s) * HD);
    float x1 = base[i];
    float x2 = base[i + 128];
    base[i]       = x1 * cv - x2 * sv;
    base[i + 128] = x2 * cv + x1 * sv;
}

// ---------------------------------------------------------------------------
// Flash-style causal attention with tanh softcap. Block = (head, q-tile pair).
// Each block processes q-tiles bx and 63-bx -> exactly 65 k-tiles of work,
// perfectly uniform across the 32x8 grid. 64x64 score tiles, fp32.
// ---------------------------------------------------------------------------
__global__ __launch_bounds__(256, 2) void attn_kernel()
{
    __shared__ float Qs[64 * 36];
    __shared__ float Ks[64 * 36];
    __shared__ float Ps[64 * 68];
    __shared__ float Vs[8 * 256];

    const int h  = blockIdx.y;
    const int hk = h >> 1;            // GQA: 2 q heads per kv head
    const int tid = threadIdx.x;
    const int tx  = tid & 15;
    const int ty  = tid >> 4;

    const float* Qh = g_q + (size_t)h  * S_LEN * HD;
    const float* Kh = g_k + (size_t)hk * S_LEN * HD;
    const float* Vh = g_v + (size_t)hk * S_LEN * HD;

    const int lr = tid >> 2;          // 0..63 row for Q/K smem loads
    const int lc = (tid & 3) * 8;     // col base (0,8,16,24)

    for (int half = 0; half < 2; half++) {
        const int qt = half ? (63 - blockIdx.x) : blockIdx.x;
        const int q0 = qt * 64;

        float m[4], l[4], acc[4][16];
#pragma unroll
        for (int r = 0; r < 4; r++) {
            m[r] = -3.0e38f; l[r] = 0.f;
#pragma unroll
            for (int u = 0; u < 16; u++) acc[r][u] = 0.f;
        }

        for (int kb = 0; kb <= qt; kb++) {
            const int k0 = kb * 64;
            float sacc[4][4];
#pragma unroll
            for (int r = 0; r < 4; r++)
#pragma unroll
                for (int c = 0; c < 4; c++) sacc[r][c] = 0.f;

            // ---- S = Q @ K^T over d in chunks of 32 ----
            for (int dk = 0; dk < HD; dk += 32) {
                float4 qa  = *(const float4*)&Qh[(size_t)(q0 + lr) * HD + dk + lc];
                float4 qb  = *(const float4*)&Qh[(size_t)(q0 + lr) * HD + dk + lc + 4];
                float4 ka  = *(const float4*)&Kh[(size_t)(k0 + lr) * HD + dk + lc];
                float4 kb4 = *(const float4*)&Kh[(size_t)(k0 + lr) * HD + dk + lc + 4];
                __syncthreads();
                *(float4*)&Qs[lr * 36 + lc]     = qa;
                *(float4*)&Qs[lr * 36 + lc + 4] = qb;
                *(float4*)&Ks[lr * 36 + lc]     = ka;
                *(float4*)&Ks[lr * 36 + lc + 4] = kb4;
                __syncthreads();
#pragma unroll
                for (int kk = 0; kk < 32; kk++) {
                    float qr[4], kr[4];
#pragma unroll
                    for (int r = 0; r < 4; r++) qr[r] = Qs[(ty * 4 + r) * 36 + kk];
#pragma unroll
                    for (int c = 0; c < 4; c++) kr[c] = Ks[(tx * 4 + c) * 36 + kk];
#pragma unroll
                    for (int r = 0; r < 4; r++)
#pragma unroll
                        for (int c = 0; c < 4; c++) sacc[r][c] += qr[r] * kr[c];
                }
            }

            // ---- softcap + causal mask + online softmax ----
#pragma unroll
            for (int r = 0; r < 4; r++) {
                const int qrow = q0 + ty * 4 + r;
                float sv[4];
#pragma unroll
                for (int c = 0; c < 4; c++) {
                    float x = sacc[r][c] * 0.0625f;     // 256^-0.5
                    x = 50.f * tanhf(x * 0.02f);        // softcap
                    int kcol = k0 + tx * 4 + c;
                    if (kcol > qrow) x = -1.0e30f;      // causal
                    sv[c] = x;
                }
                float mx = fmaxf(fmaxf(sv[0], sv[1]), fmaxf(sv[2], sv[3]));
#pragma unroll
                for (int off = 1; off < 16; off <<= 1)
                    mx = fmaxf(mx, __shfl_xor_sync(0xffffffffu, mx, off));
                float mn = fmaxf(m[r], mx);
                float rescale = expf(m[r] - mn);
                float psum = 0.f;
#pragma unroll
                for (int c = 0; c < 4; c++) {
                    float pv = expf(sv[c] - mn);
                    Ps[(ty * 4 + r) * 68 + tx * 4 + c] = pv;
                    psum += pv;
                }
#pragma unroll
                for (int off = 1; off < 16; off <<= 1)
                    psum += __shfl_xor_sync(0xffffffffu, psum, off);
                l[r] = l[r] * rescale + psum;
                m[r] = mn;
#pragma unroll
                for (int u = 0; u < 16; u++) acc[r][u] *= rescale;
            }

            // ---- O += P @ V, V staged in 8-row smem chunks ----
            for (int jc = 0; jc < 64; jc += 8) {
                int f0 = tid, f1 = tid + 256;
                int r0 = f0 >> 6, c0 = (f0 & 63) * 4;
                int r1 = f1 >> 6, c1 = (f1 & 63) * 4;
                float4 v0 = *(const float4*)&Vh[(size_t)(k0 + jc + r0) * HD + c0];
                float4 v1 = *(const float4*)&Vh[(size_t)(k0 + jc + r1) * HD + c1];
                __syncthreads();   // also publishes Ps on the first chunk
                *(float4*)&Vs[r0 * 256 + c0] = v0;
                *(float4*)&Vs[r1 * 256 + c1] = v1;
                __syncthreads();
#pragma unroll
                for (int jj = 0; jj < 8; jj++) {
                    float vv[16];
#pragma unroll
                    for (int u = 0; u < 16; u++) vv[u] = Vs[jj * 256 + u * 16 + tx];
#pragma unroll
                    for (int r = 0; r < 4; r++) {
                        float pw = Ps[(ty * 4 + r) * 68 + jc + jj];
#pragma unroll
                        for (int u = 0; u < 16; u++) acc[r][u] += pw * vv[u];
                    }
                }
            }
        }

        // ---- epilogue: normalize and write [s][h*HD+d] ----
#pragma unroll
        for (int r = 0; r < 4; r++) {
            float inv = 1.f / l[r];
            int srow = q0 + ty * 4 + r;
#pragma unroll
            for (int u = 0; u < 16; u++)
                g_attn[(size_t)srow * (NH * HD) + h * HD + u * 16 + tx] = acc[r][u] * inv;
        }
        __syncthreads();
    }
}

// ---------------------------------------------------------------------------
extern "C" void kernel_launch(void* const* d_in, const int* in_sizes, int n_in,
                              void* d_out, int out_size)
{
    const float* hs  = (const float*)d_in[0];
    // d_in[1] = attention_mask: pure causal (window >= S), recomputed in-kernel
    const void*  pos = d_in[2];      // int32 or int64, detected in-kernel
    const float* wq  = (const float*)d_in[3];
    const float* wk  = (const float*)d_in[4];
    const float* wv  = (const float*)d_in[5];
    const float* wo  = (const float*)d_in[6];
    float* out = (float*)d_out;

    float *pq, *pk, *pv, *pa;
    cudaGetSymbolAddress((void**)&pq, g_q);
    cudaGetSymbolAddress((void**)&pk, g_k);
    cudaGetSymbolAddress((void**)&pv, g_v);
    cudaGetSymbolAddress((void**)&pa, g_attn);

    dim3 blk(256);
    // QKV projections -> headed layouts
    sgemm_kernel<<<dim3(2048 / 128, S_LEN / 128), blk>>>(hs, wq, nullptr, pq,
                                                         S_LEN, 2048, HIDDEN, 1);
    sgemm_kernel<<<dim3(1024 / 128, S_LEN / 128), blk>>>(hs, wk, nullptr, pk,
                                                         S_LEN, 1024, HIDDEN, 1);
    sgemm_kernel<<<dim3(1024 / 128, S_LEN / 128), blk>>>(hs, wv, nullptr, pv,
                                                         S_LEN, 1024, HIDDEN, 1);
    // RoPE on q and k in place
    rope_kernel<<<((NH + NKV) * S_LEN * (HD / 2)) / 256, 256>>>(pos);
    // Causal flash attention with tanh softcap
    attn_kernel<<<dim3(32, NH), blk>>>();
    // Output projection
    sgemm_kernel<<<dim3(2048 / 128, S_LEN / 128), blk>>>(pa, wo, out, nullptr,
                                                         S_LEN, HIDDEN, NH * HD, 0);
}

// round 3
// speedup vs baseline: 1.5194x; 1.5194x over previous
#include <cuda_runtime.h>
#include <cuda_bf16.h>
#include <math.h>
#include <stdint.h>

#define S_LEN 4096
#define HIDDEN 2048
#define NH 8
#define NKV 4
#define HD 256

// Scratch (allocation-free: device globals)
__device__ float g_q[(size_t)NH * S_LEN * HD];      // [h][s][d]
__device__ float g_k[(size_t)NKV * S_LEN * HD];     // [h][s][d]
__device__ float g_v[(size_t)NKV * S_LEN * HD];     // [h][s][d]
__device__ float g_attn[(size_t)S_LEN * (NH * HD)]; // [s][h*HD+d], tf32-rounded
// tf32-rounded copies of inputs (cvt.rna once, GEMMs read these)
__device__ float g_hs_r[(size_t)S_LEN * HIDDEN];
__device__ float g_wq_r[(size_t)HIDDEN * (NH * HD)];
__device__ float g_wk_r[(size_t)HIDDEN * (NKV * HD)];
__device__ float g_wv_r[(size_t)HIDDEN * (NKV * HD)];
__device__ float g_wo_r[(size_t)(NH * HD) * HIDDEN];

__device__ __forceinline__ float to_tf32(float x) {
    float r;
    asm("cvt.rna.tf32.f32 %0, %1;" : "=f"(r) : "f"(x));
    return r;
}

// ---------------------------------------------------------------------------
// Prepass: round fp32 -> tf32-in-fp32 (rna), vectorized. n % 1024 == 0.
// ---------------------------------------------------------------------------
__global__ void round_tf32_kernel(const float* __restrict__ in,
                                  float* __restrict__ out, int n4)
{
    int i = blockIdx.x * blockDim.x + threadIdx.x;
    if (i >= n4) return;
    float4 v = ((const float4*)in)[i];
    v.x = to_tf32(v.x); v.y = to_tf32(v.y);
    v.z = to_tf32(v.z); v.w = to_tf32(v.w);
    ((float4*)out)[i] = v;
}

// ---------------------------------------------------------------------------
// tf32 tensor-core GEMM: C[M,N] = A[M,K] @ B[K,N], both row-major, inputs
// already tf32-rounded. 128x128 block tile, BK=32, 256 threads = 8 warps
// (4 in m x 2 in n); each warp computes 32x64 via m16n8k8 mma.sync.
// headed=1 writes to [n>>8][m][n&255] layout (per-head q/k/v).
// ---------------------------------------------------------------------------
__global__ __launch_bounds__(256) void tf32_gemm_kernel(
    const float* __restrict__ A, const float* __restrict__ B,
    float* __restrict__ Cplain, float* __restrict__ Chead,
    int M, int N, int K, int headed)
{
    __shared__ float As[128 * 36];   // row-major, stride 36 (conflict-free frags)
    __shared__ float Bs[32 * 136];   // row-major, stride 136 (conflict-free frags)

    const int tid  = threadIdx.x;
    const int lane = tid & 31;
    const int wid  = tid >> 5;
    const int wm   = (wid & 3) * 32;   // warp m offset
    const int wn   = (wid >> 2) * 64;  // warp n offset
    const int bm   = blockIdx.y * 128;
    const int bn   = blockIdx.x * 128;

    const int grp  = lane >> 2;  // 0..7
    const int qd   = lane & 3;   // 0..3

    float c[2][8][4];
#pragma unroll
    for (int mt = 0; mt < 2; mt++)
#pragma unroll
        for (int nt = 0; nt < 8; nt++)
#pragma unroll
            for (int r = 0; r < 4; r++) c[mt][nt][r] = 0.f;

    const uint32_t* Asu = (const uint32_t*)As;
    const uint32_t* Bsu = (const uint32_t*)Bs;

    for (int k0 = 0; k0 < K; k0 += 32) {
        // gmem prefetch into regs: A 128x32, B 32x128 (1024 float4 each)
        float4 av[4], bv[4];
#pragma unroll
        for (int p = 0; p < 4; p++) {
            int ia = tid + p * 256;
            int ar = ia >> 3, ac4 = ia & 7;
            av[p] = *(const float4*)&A[(size_t)(bm + ar) * K + k0 + ac4 * 4];
            int br = ia >> 5, bc4 = ia & 31;
            bv[p] = *(const float4*)&B[(size_t)(k0 + br) * N + bn + bc4 * 4];
        }
        __syncthreads();
#pragma unroll
        for (int p = 0; p < 4; p++) {
            int ia = tid + p * 256;
            int ar = ia >> 3, ac4 = ia & 7;
            *(float4*)&As[ar * 36 + ac4 * 4] = av[p];
            int br = ia >> 5, bc4 = ia & 31;
            *(float4*)&Bs[br * 136 + bc4 * 4] = bv[p];
        }
        __syncthreads();

#pragma unroll
        for (int ks = 0; ks < 4; ks++) {
            const int kc = ks * 8 + qd;
            uint32_t a[2][4];
#pragma unroll
            for (int mt = 0; mt < 2; mt++) {
                int r0 = wm + mt * 16 + grp;
                a[mt][0] = Asu[r0 * 36 + kc];
                a[mt][1] = Asu[(r0 + 8) * 36 + kc];
                a[mt][2] = Asu[r0 * 36 + kc + 4];
                a[mt][3] = Asu[(r0 + 8) * 36 + kc + 4];
            }
            uint32_t b[8][2];
#pragma unroll
            for (int nt = 0; nt < 8; nt++) {
                int nc = wn + nt * 8 + grp;
                b[nt][0] = Bsu[(ks * 8 + qd) * 136 + nc];
                b[nt][1] = Bsu[(ks * 8 + qd + 4) * 136 + nc];
            }
#pragma unroll
            for (int mt = 0; mt < 2; mt++)
#pragma unroll
                for (int nt = 0; nt < 8; nt++) {
                    asm volatile(
                        "mma.sync.aligned.m16n8k8.row.col.f32.tf32.tf32.f32 "
                        "{%0,%1,%2,%3}, {%4,%5,%6,%7}, {%8,%9}, {%0,%1,%2,%3};"
                        : "+f"(c[mt][nt][0]), "+f"(c[mt][nt][1]),
                          "+f"(c[mt][nt][2]), "+f"(c[mt][nt][3])
                        : "r"(a[mt][0]), "r"(a[mt][1]), "r"(a[mt][2]), "r"(a[mt][3]),
                          "r"(b[nt][0]), "r"(b[nt][1]));
                }
        }
    }

    // epilogue: c0,c1 at (m, n),(m,n+1); c2,c3 at (m+8, n),(m+8,n+1)
    const int m0 = bm + wm + grp;
    const int n0 = bn + wn + 2 * qd;
    if (headed) {
#pragma unroll
        for (int mt = 0; mt < 2; mt++)
#pragma unroll
            for (int nt = 0; nt < 8; nt++) {
                int m = m0 + mt * 16;
                int n = n0 + nt * 8;
                size_t base = (size_t)(n >> 8) * ((size_t)M * HD) + (n & 255);
                *(float2*)&Chead[base + (size_t)m * HD] =
                    make_float2(c[mt][nt][0], c[mt][nt][1]);
                *(float2*)&Chead[base + (size_t)(m + 8) * HD] =
                    make_float2(c[mt][nt][2], c[mt][nt][3]);
            }
    } else {
#pragma unroll
        for (int mt = 0; mt < 2; mt++)
#pragma unroll
            for (int nt = 0; nt < 8; nt++) {
                int m = m0 + mt * 16;
                int n = n0 + nt * 8;
                *(float2*)&Cplain[(size_t)m * N + n] =
                    make_float2(c[mt][nt][0], c[mt][nt][1]);
                *(float2*)&Cplain[(size_t)(m + 8) * N + n] =
                    make_float2(c[mt][nt][2], c[mt][nt][3]);
            }
    }
}

// ---------------------------------------------------------------------------
// RoPE: one thread per (s, i) computes cos/sin once (fp64 range reduction,
// accurate under fast-math) and applies to all 8 q heads + 4 k heads.
// Also folds SCALING = 256^-0.5 = 0.0625 into q.
// position_ids may be int32 (JAX default) or int64; detect via word[1]==0.
// ---------------------------------------------------------------------------
__global__ void rope_kernel(const void* __restrict__ pos_raw)
{
    int idx = blockIdx.x * blockDim.x + threadIdx.x;
    if (idx >= S_LEN * 128) return;
    int i = idx & 127;       // frequency index
    int s = idx >> 7;        // sequence position

    const int* p32 = (const int*)pos_raw;
    long long pll = (p32[1] == 0) ? ((const long long*)pos_raw)[s]
                                  : (long long)p32[s];
    float p = (float)pll;

    double invd = exp(-(double)i * (9.210340371976184 / 128.0)); // 10000^(-i/128)
    float f = (float)((double)p * invd);  // fp32 freq like reference
    const double TWO_PI = 6.283185307179586476925287;
    double r = (double)f;
    r -= TWO_PI * floor(r / TWO_PI);
    float sv = sinf((float)r);
    float cv = cosf((float)r);

#pragma unroll
    for (int h = 0; h < NH; h++) {
        float* base = g_q + ((size_t)h * S_LEN + s) * HD;
        float x1 = base[i], x2 = base[i + 128];
        base[i]       = (x1 * cv - x2 * sv) * 0.0625f;
        base[i + 128] = (x2 * cv + x1 * sv) * 0.0625f;
    }
#pragma unroll
    for (int h = 0; h < NKV; h++) {
        float* base = g_k + ((size_t)h * S_LEN + s) * HD;
        float x1 = base[i], x2 = base[i + 128];
        base[i]       = x1 * cv - x2 * sv;
        base[i + 128] = x2 * cv + x1 * sv;
    }
}

// ---------------------------------------------------------------------------
// Flash-style causal attention with tanh softcap (fp32 SIMT). Block =
// (head, q-tile pair): q-tiles bx and 63-bx -> exactly 65 k-tiles per block,
// uniform over the 32x8 grid. Scaling pre-folded into q. Output rounded to
// tf32 for the tensor-core O-projection.
// ---------------------------------------------------------------------------
__global__ __launch_bounds__(256, 2) void attn_kernel()
{
    __shared__ float Qs[64 * 36];
    __shared__ float Ks[64 * 36];
    __shared__ float Ps[64 * 68];
    __shared__ float Vs[8 * 256];

    const int h  = blockIdx.y;
    const int hk = h >> 1;            // GQA: 2 q heads per kv head
    const int tid = threadIdx.x;
    const int tx  = tid & 15;
    const int ty  = tid >> 4;

    const float* Qh = g_q + (size_t)h  * S_LEN * HD;
    const float* Kh = g_k + (size_t)hk * S_LEN * HD;
    const float* Vh = g_v + (size_t)hk * S_LEN * HD;

    const int lr = tid >> 2;          // 0..63 row for Q/K smem loads
    const int lc = (tid & 3) * 8;     // col base (0,8,16,24)

    for (int half = 0; half < 2; half++) {
        const int qt = half ? (63 - blockIdx.x) : blockIdx.x;
        const int q0 = qt * 64;

        float m[4], l[4], acc[4][16];
#pragma unroll
        for (int r = 0; r < 4; r++) {
            m[r] = -3.0e38f; l[r] = 0.f;
#pragma unroll
            for (int u = 0; u < 16; u++) acc[r][u] = 0.f;
        }

        for (int kb = 0; kb <= qt; kb++) {
            const int k0 = kb * 64;
            float sacc[4][4];
#pragma unroll
            for (int r = 0; r < 4; r++)
#pragma unroll
                for (int cc = 0; cc < 4; cc++) sacc[r][cc] = 0.f;

            // ---- S = Q @ K^T over d in chunks of 32 ----
            for (int dk = 0; dk < HD; dk += 32) {
                float4 qa  = *(const float4*)&Qh[(size_t)(q0 + lr) * HD + dk + lc];
                float4 qb  = *(const float4*)&Qh[(size_t)(q0 + lr) * HD + dk + lc + 4];
                float4 ka  = *(const float4*)&Kh[(size_t)(k0 + lr) * HD + dk + lc];
                float4 kb4 = *(const float4*)&Kh[(size_t)(k0 + lr) * HD + dk + lc + 4];
                __syncthreads();
                *(float4*)&Qs[lr * 36 + lc]     = qa;
                *(float4*)&Qs[lr * 36 + lc + 4] = qb;
                *(float4*)&Ks[lr * 36 + lc]     = ka;
                *(float4*)&Ks[lr * 36 + lc + 4] = kb4;
                __syncthreads();
#pragma unroll
                for (int kk = 0; kk < 32; kk++) {
                    float qr[4], kr[4];
#pragma unroll
                    for (int r = 0; r < 4; r++) qr[r] = Qs[(ty * 4 + r) * 36 + kk];
#pragma unroll
                    for (int cc = 0; cc < 4; cc++) kr[cc] = Ks[(tx * 4 + cc) * 36 + kk];
#pragma unroll
                    for (int r = 0; r < 4; r++)
#pragma unroll
                        for (int cc = 0; cc < 4; cc++) sacc[r][cc] += qr[r] * kr[cc];
                }
            }

            // ---- softcap + causal mask + online softmax ----
#pragma unroll
            for (int r = 0; r < 4; r++) {
                const int qrow = q0 + ty * 4 + r;
                float sv[4];
#pragma unroll
                for (int cc = 0; cc < 4; cc++) {
                    float x = sacc[r][cc];              // scaling pre-folded in q
                    x = 50.f * tanhf(x * 0.02f);        // softcap
                    int kcol = k0 + tx * 4 + cc;
                    if (kcol > qrow) x = -1.0e30f;      // causal
                    sv[cc] = x;
                }
                float mx = fmaxf(fmaxf(sv[0], sv[1]), fmaxf(sv[2], sv[3]));
#pragma unroll
                for (int off = 1; off < 16; off <<= 1)
                    mx = fmaxf(mx, __shfl_xor_sync(0xffffffffu, mx, off));
                float mn = fmaxf(m[r], mx);
                float rescale = expf(m[r] - mn);
                float psum = 0.f;
#pragma unroll
                for (int cc = 0; cc < 4; cc++) {
                    float pv = expf(sv[cc] - mn);
                    Ps[(ty * 4 + r) * 68 + tx * 4 + cc] = pv;
                    psum += pv;
                }
#pragma unroll
                for (int off = 1; off < 16; off <<= 1)
                    psum += __shfl_xor_sync(0xffffffffu, psum, off);
                l[r] = l[r] * rescale + psum;
                m[r] = mn;
#pragma unroll
                for (int u = 0; u < 16; u++) acc[r][u] *= rescale;
            }

            // ---- O += P @ V, V staged in 8-row smem chunks ----
            for (int jc = 0; jc < 64; jc += 8) {
                int f0 = tid, f1 = tid + 256;
                int r0 = f0 >> 6, c0 = (f0 & 63) * 4;
                int r1 = f1 >> 6, c1 = (f1 & 63) * 4;
                float4 v0 = *(const float4*)&Vh[(size_t)(k0 + jc + r0) * HD + c0];
                float4 v1 = *(const float4*)&Vh[(size_t)(k0 + jc + r1) * HD + c1];
                __syncthreads();   // also publishes Ps on the first chunk
                *(float4*)&Vs[r0 * 256 + c0] = v0;
                *(float4*)&Vs[r1 * 256 + c1] = v1;
                __syncthreads();
#pragma unroll
                for (int jj = 0; jj < 8; jj++) {
                    float vv[16];
#pragma unroll
                    for (int u = 0; u < 16; u++) vv[u] = Vs[jj * 256 + u * 16 + tx];
#pragma unroll
                    for (int r = 0; r < 4; r++) {
                        float pw = Ps[(ty * 4 + r) * 68 + jc + jj];
#pragma unroll
                        for (int u = 0; u < 16; u++) acc[r][u] += pw * vv[u];
                    }
                }
            }
        }

        // ---- epilogue: normalize, round to tf32, write [s][h*HD+d] ----
#pragma unroll
        for (int r = 0; r < 4; r++) {
            float inv = 1.f / l[r];
            int srow = q0 + ty * 4 + r;
#pragma unroll
            for (int u = 0; u < 16; u++)
                g_attn[(size_t)srow * (NH * HD) + h * HD + u * 16 + tx] =
                    to_tf32(acc[r][u] * inv);
        }
        __syncthreads();
    }
}

// ---------------------------------------------------------------------------
extern "C" void kernel_launch(void* const* d_in, const int* in_sizes, int n_in,
                              void* d_out, int out_size)
{
    const float* hs  = (const float*)d_in[0];
    // d_in[1] = attention_mask: pure causal (window >= S), recomputed in-kernel
    const void*  pos = d_in[2];      // int32 or int64, detected in-kernel
    const float* wq  = (const float*)d_in[3];
    const float* wk  = (const float*)d_in[4];
    const float* wv  = (const float*)d_in[5];
    const float* wo  = (const float*)d_in[6];
    float* out = (float*)d_out;

    float *pq, *pk, *pv, *pa, *phs, *pwq, *pwk, *pwv, *pwo;
    cudaGetSymbolAddress((void**)&pq,  g_q);
    cudaGetSymbolAddress((void**)&pk,  g_k);
    cudaGetSymbolAddress((void**)&pv,  g_v);
    cudaGetSymbolAddress((void**)&pa,  g_attn);
    cudaGetSymbolAddress((void**)&phs, g_hs_r);
    cudaGetSymbolAddress((void**)&pwq, g_wq_r);
    cudaGetSymbolAddress((void**)&pwk, g_wk_r);
    cudaGetSymbolAddress((void**)&pwv, g_wv_r);
    cudaGetSymbolAddress((void**)&pwo, g_wo_r);

    // Prepass: tf32-round inputs (n/4 threads, vectorized)
    auto roundN = [&](const float* in, float* o, size_t n) {
        int n4 = (int)(n / 4);
        round_tf32_kernel<<<(n4 + 255) / 256, 256>>>(in, o, n4);
    };
    roundN(hs, phs, (size_t)S_LEN * HIDDEN);
    roundN(wq, pwq, (size_t)HIDDEN * 2048);
    roundN(wk, pwk, (size_t)HIDDEN * 1024);
    roundN(wv, pwv, (size_t)HIDDEN * 1024);
    roundN(wo, pwo, (size_t)2048 * HIDDEN);

    dim3 blk(256);
    // QKV projections -> headed layouts (tensor cores, tf32)
    tf32_gemm_kernel<<<dim3(2048 / 128, S_LEN / 128), blk>>>(phs, pwq, nullptr, pq,
                                                             S_LEN, 2048, HIDDEN, 1);
    tf32_gemm_kernel<<<dim3(1024 / 128, S_LEN / 128), blk>>>(phs, pwk, nullptr, pk,
                                                             S_LEN, 1024, HIDDEN, 1);
    tf32_gemm_kernel<<<dim3(1024 / 128, S_LEN / 128), blk>>>(phs, pwv, nullptr, pv,
                                                             S_LEN, 1024, HIDDEN, 1);
    // RoPE on q and k in place (+ fold attention scaling into q)
    rope_kernel<<<(S_LEN * 128) / 256, 256>>>(pos);
    // Causal flash attention with tanh softcap
    attn_kernel<<<dim3(32, NH), blk>>>();
    // Output projection (tensor cores, tf32)
    tf32_gemm_kernel<<<dim3(2048 / 128, S_LEN / 128), blk>>>(pa, pwo, out, nullptr,
                                                             S_LEN, HIDDEN, 2048, 0);
}

// round 4
// speedup vs baseline: 4.1524x; 2.7329x over previous
#include <cuda_runtime.h>
#include <cuda_bf16.h>
#include <math.h>
#include <stdint.h>

#define S_LEN 4096
#define HIDDEN 2048
#define NH 8
#define NKV 4
#define HD 256

// Scratch (allocation-free: device globals)
__device__ float g_q[(size_t)NH * S_LEN * HD];      // [h][s][d], tf32-rounded
__device__ float g_k[(size_t)NKV * S_LEN * HD];     // [h][s][d], tf32-rounded
__device__ float g_v[(size_t)NKV * S_LEN * HD];     // [h][s][d], tf32-rounded
__device__ float g_attn[(size_t)S_LEN * (NH * HD)]; // [s][h*HD+d], tf32-rounded
// tf32-rounded copies of inputs
__device__ float g_hs_r[(size_t)S_LEN * HIDDEN];
__device__ float g_wq_r[(size_t)HIDDEN * (NH * HD)];
__device__ float g_wk_r[(size_t)HIDDEN * (NKV * HD)];
__device__ float g_wv_r[(size_t)HIDDEN * (NKV * HD)];
__device__ float g_wo_r[(size_t)(NH * HD) * HIDDEN];

__device__ __forceinline__ float to_tf32(float x) {
    float r;
    asm("cvt.rna.tf32.f32 %0, %1;" : "=f"(r) : "f"(x));
    return r;
}

#define MMA_TF32(C, A, B0, B1)                                              \
    asm volatile(                                                           \
        "mma.sync.aligned.m16n8k8.row.col.f32.tf32.tf32.f32 "               \
        "{%0,%1,%2,%3}, {%4,%5,%6,%7}, {%8,%9}, {%0,%1,%2,%3};"             \
        : "+f"((C)[0]), "+f"((C)[1]), "+f"((C)[2]), "+f"((C)[3])            \
        : "r"((A)[0]), "r"((A)[1]), "r"((A)[2]), "r"((A)[3]),               \
          "r"(B0), "r"(B1))

// ---------------------------------------------------------------------------
// Prepass: round fp32 -> tf32-in-fp32 (rna), vectorized.
// ---------------------------------------------------------------------------
__global__ void round_tf32_kernel(const float* __restrict__ in,
                                  float* __restrict__ out, int n4)
{
    int i = blockIdx.x * blockDim.x + threadIdx.x;
    if (i >= n4) return;
    float4 v = ((const float4*)in)[i];
    v.x = to_tf32(v.x); v.y = to_tf32(v.y);
    v.z = to_tf32(v.z); v.w = to_tf32(v.w);
    ((float4*)out)[i] = v;
}

// ---------------------------------------------------------------------------
// tf32 tensor-core GEMM: C[M,N] = A[M,K] @ B[K,N]. 128x128 tile, BK=32,
// 8 warps (4m x 2n), m16n8k8. headed=1 -> [n>>8][m][n&255] layout, rounded
// to tf32 (q/k/v feed tensor-core attention).
// ---------------------------------------------------------------------------
__global__ __launch_bounds__(256) void tf32_gemm_kernel(
    const float* __restrict__ A, const float* __restrict__ B,
    float* __restrict__ Cplain, float* __restrict__ Chead,
    int M, int N, int K, int headed)
{
    __shared__ float As[128 * 36];
    __shared__ float Bs[32 * 136];

    const int tid  = threadIdx.x;
    const int lane = tid & 31;
    const int wid  = tid >> 5;
    const int wm   = (wid & 3) * 32;
    const int wn   = (wid >> 2) * 64;
    const int bm   = blockIdx.y * 128;
    const int bn   = blockIdx.x * 128;
    const int grp  = lane >> 2;
    const int qd   = lane & 3;

    float c[2][8][4];
#pragma unroll
    for (int mt = 0; mt < 2; mt++)
#pragma unroll
        for (int nt = 0; nt < 8; nt++)
#pragma unroll
            for (int r = 0; r < 4; r++) c[mt][nt][r] = 0.f;

    const uint32_t* Asu = (const uint32_t*)As;
    const uint32_t* Bsu = (const uint32_t*)Bs;

    for (int k0 = 0; k0 < K; k0 += 32) {
        float4 av[4], bv[4];
#pragma unroll
        for (int p = 0; p < 4; p++) {
            int ia = tid + p * 256;
            int ar = ia >> 3, ac4 = ia & 7;
            av[p] = *(const float4*)&A[(size_t)(bm + ar) * K + k0 + ac4 * 4];
            int br = ia >> 5, bc4 = ia & 31;
            bv[p] = *(const float4*)&B[(size_t)(k0 + br) * N + bn + bc4 * 4];
        }
        __syncthreads();
#pragma unroll
        for (int p = 0; p < 4; p++) {
            int ia = tid + p * 256;
            int ar = ia >> 3, ac4 = ia & 7;
            *(float4*)&As[ar * 36 + ac4 * 4] = av[p];
            int br = ia >> 5, bc4 = ia & 31;
            *(float4*)&Bs[br * 136 + bc4 * 4] = bv[p];
        }
        __syncthreads();

#pragma unroll
        for (int ks = 0; ks < 4; ks++) {
            const int kc = ks * 8 + qd;
            uint32_t a[2][4];
#pragma unroll
            for (int mt = 0; mt < 2; mt++) {
                int r0 = wm + mt * 16 + grp;
                a[mt][0] = Asu[r0 * 36 + kc];
                a[mt][1] = Asu[(r0 + 8) * 36 + kc];
                a[mt][2] = Asu[r0 * 36 + kc + 4];
                a[mt][3] = Asu[(r0 + 8) * 36 + kc + 4];
            }
#pragma unroll
            for (int nt = 0; nt < 8; nt++) {
                int nc = wn + nt * 8 + grp;
                uint32_t b0 = Bsu[kc * 136 + nc];
                uint32_t b1 = Bsu[(kc + 4) * 136 + nc];
#pragma unroll
                for (int mt = 0; mt < 2; mt++)
                    MMA_TF32(c[mt][nt], a[mt], b0, b1);
            }
        }
    }

    const int m0 = bm + wm + grp;
    const int n0 = bn + wn + 2 * qd;
    if (headed) {
#pragma unroll
        for (int mt = 0; mt < 2; mt++)
#pragma unroll
            for (int nt = 0; nt < 8; nt++) {
                int m = m0 + mt * 16;
                int n = n0 + nt * 8;
                size_t base = (size_t)(n >> 8) * ((size_t)M * HD) + (n & 255);
                *(float2*)&Chead[base + (size_t)m * HD] =
                    make_float2(to_tf32(c[mt][nt][0]), to_tf32(c[mt][nt][1]));
                *(float2*)&Chead[base + (size_t)(m + 8) * HD] =
                    make_float2(to_tf32(c[mt][nt][2]), to_tf32(c[mt][nt][3]));
            }
    } else {
#pragma unroll
        for (int mt = 0; mt < 2; mt++)
#pragma unroll
            for (int nt = 0; nt < 8; nt++) {
                int m = m0 + mt * 16;
                int n = n0 + nt * 8;
                *(float2*)&Cplain[(size_t)m * N + n] =
                    make_float2(c[mt][nt][0], c[mt][nt][1]);
                *(float2*)&Cplain[(size_t)(m + 8) * N + n] =
                    make_float2(c[mt][nt][2], c[mt][nt][3]);
            }
    }
}

// ---------------------------------------------------------------------------
// RoPE: one thread per (s, i); cos/sin computed once (fp64 range reduction),
// applied to all 12 heads. Folds SCALING=0.0625 into q. Rounds outputs to
// tf32 (rna) for the attention MMAs. position_ids int32/int64 auto-detected.
// ---------------------------------------------------------------------------
__global__ void rope_kernel(const void* __restrict__ pos_raw)
{
    int idx = blockIdx.x * blockDim.x + threadIdx.x;
    if (idx >= S_LEN * 128) return;
    int i = idx & 127;
    int s = idx >> 7;

    const int* p32 = (const int*)pos_raw;
    long long pll = (p32[1] == 0) ? ((const long long*)pos_raw)[s]
                                  : (long long)p32[s];
    float p = (float)pll;

    double invd = exp(-(double)i * (9.210340371976184 / 128.0));
    float f = (float)((double)p * invd);
    const double TWO_PI = 6.283185307179586476925287;
    double r = (double)f;
    r -= TWO_PI * floor(r / TWO_PI);
    float sv = sinf((float)r);
    float cv = cosf((float)r);

#pragma unroll
    for (int h = 0; h < NH; h++) {
        float* base = g_q + ((size_t)h * S_LEN + s) * HD;
        float x1 = base[i], x2 = base[i + 128];
        base[i]       = to_tf32((x1 * cv - x2 * sv) * 0.0625f);
        base[i + 128] = to_tf32((x2 * cv + x1 * sv) * 0.0625f);
    }
#pragma unroll
    for (int h = 0; h < NKV; h++) {
        float* base = g_k + ((size_t)h * S_LEN + s) * HD;
        float x1 = base[i], x2 = base[i + 128];
        base[i]       = to_tf32(x1 * cv - x2 * sv);
        base[i + 128] = to_tf32(x2 * cv + x1 * sv);
    }
}

// ---------------------------------------------------------------------------
// Tensor-core flash attention with tanh softcap. Block = (head, q-tile pair),
// q-tiles bx and 63-bx -> 65 k-blocks per block, uniform over 32x8 grid.
// Q/K/V tiles resident in smem (222.7 KB dynamic). 8 warps: (wr 4 x wc 2).
// QK: warp computes S rows [wr*16,+16) cols [wc*32,+32).
// PV: warp computes O rows [wr*16,+16) cols [wc*128,+128).
// Softmax: SIMT, thread (ty,tx) owns rows ty*4..+3, cols tx*4..+3.
// smem float offsets (strides chosen lane-bijective mod 32 for frag loads):
//   Qf 64x268, Kf 64x268, Ss 64x68, Vs 64x264, rs 64, linv 64.
// ---------------------------------------------------------------------------
#define QK_STRIDE 268
#define V_STRIDE  264
#define S_STRIDE  68
#define OFF_QF 0
#define OFF_KF (64 * QK_STRIDE)
#define OFF_SS (OFF_KF + 64 * QK_STRIDE)
#define OFF_VS (OFF_SS + 64 * S_STRIDE)
#define OFF_RS (OFF_VS + 64 * V_STRIDE)
#define OFF_LI (OFF_RS + 64)
#define ATTN_SMEM_FLOATS (OFF_LI + 64)

__global__ __launch_bounds__(256) void attn_mma_kernel()
{
    extern __shared__ float sm[];
    float* Qf = sm + OFF_QF;
    float* Kf = sm + OFF_KF;
    float* Ss = sm + OFF_SS;
    float* Vs = sm + OFF_VS;
    float* rs = sm + OFF_RS;
    float* li = sm + OFF_LI;
    const uint32_t* Qfu = (const uint32_t*)Qf;
    const uint32_t* Kfu = (const uint32_t*)Kf;
    const uint32_t* Ssu = (const uint32_t*)Ss;
    const uint32_t* Vsu = (const uint32_t*)Vs;

    const int h  = blockIdx.y;
    const int hk = h >> 1;
    const int tid  = threadIdx.x;
    const int lane = tid & 31;
    const int wid  = tid >> 5;
    const int wr   = wid & 3;
    const int wc   = wid >> 2;
    const int grp  = lane >> 2;
    const int qd   = lane & 3;
    const int r0   = wr * 16 + grp;
    const int ty   = tid >> 4;
    const int tx   = tid & 15;

    const float* Qh = g_q + (size_t)h  * S_LEN * HD;
    const float* Kh = g_k + (size_t)hk * S_LEN * HD;
    const float* Vh = g_v + (size_t)hk * S_LEN * HD;

    const float LOG2E = 1.4426950408889634f;

    for (int half = 0; half < 2; half++) {
        const int qt = half ? (63 - blockIdx.x) : blockIdx.x;
        const int q0 = qt * 64;

        // load Q tile once per q-tile
        __syncthreads();
#pragma unroll
        for (int p = 0; p < 16; p++) {
            int idx = tid + p * 256;
            int row = idx >> 6, c4 = idx & 63;
            *(float4*)&Qf[row * QK_STRIDE + c4 * 4] =
                *(const float4*)&Qh[(size_t)(q0 + row) * HD + c4 * 4];
        }

        float m[4], l[4], o[16][4];
#pragma unroll
        for (int r = 0; r < 4; r++) { m[r] = -3.0e38f; l[r] = 0.f; }
#pragma unroll
        for (int nt = 0; nt < 16; nt++)
#pragma unroll
            for (int r = 0; r < 4; r++) o[nt][r] = 0.f;

        for (int kb = 0; kb <= qt; kb++) {
            const int k0 = kb * 64;
            __syncthreads();   // prev PV reads of Vs / Q load done
            // stage K and V tiles
#pragma unroll
            for (int p = 0; p < 16; p++) {
                int idx = tid + p * 256;
                int row = idx >> 6, c4 = idx & 63;
                *(float4*)&Kf[row * QK_STRIDE + c4 * 4] =
                    *(const float4*)&Kh[(size_t)(k0 + row) * HD + c4 * 4];
                *(float4*)&Vs[row * V_STRIDE + c4 * 4] =
                    *(const float4*)&Vh[(size_t)(k0 + row) * HD + c4 * 4];
            }
            __syncthreads();

            // ---- QK: S[64][64] fragments ----
            float s[4][4];
#pragma unroll
            for (int nt = 0; nt < 4; nt++)
#pragma unroll
                for (int r = 0; r < 4; r++) s[nt][r] = 0.f;
#pragma unroll 8
            for (int ks = 0; ks < 32; ks++) {
                const int kc = ks * 8 + qd;
                uint32_t a[4];
                a[0] = Qfu[r0 * QK_STRIDE + kc];
                a[1] = Qfu[(r0 + 8) * QK_STRIDE + kc];
                a[2] = Qfu[r0 * QK_STRIDE + kc + 4];
                a[3] = Qfu[(r0 + 8) * QK_STRIDE + kc + 4];
#pragma unroll
                for (int nt = 0; nt < 4; nt++) {
                    int nc = wc * 32 + nt * 8 + grp;
                    uint32_t b0 = Kfu[nc * QK_STRIDE + kc];
                    uint32_t b1 = Kfu[nc * QK_STRIDE + kc + 4];
                    MMA_TF32(s[nt], a, b0, b1);
                }
            }
            // frags -> Ss
#pragma unroll
            for (int nt = 0; nt < 4; nt++) {
                int col = wc * 32 + nt * 8 + 2 * qd;
                *(float2*)&Ss[r0 * S_STRIDE + col] = make_float2(s[nt][0], s[nt][1]);
                *(float2*)&Ss[(r0 + 8) * S_STRIDE + col] = make_float2(s[nt][2], s[nt][3]);
            }
            __syncthreads();

            // ---- softcap + causal + online softmax (SIMT) ----
#pragma unroll
            for (int r = 0; r < 4; r++) {
                const int row = ty * 4 + r;
                const int qrow = q0 + row;
                float4 raw = *(float4*)&Ss[row * S_STRIDE + tx * 4];
                float sv[4] = {raw.x, raw.y, raw.z, raw.w};
#pragma unroll
                for (int cc = 0; cc < 4; cc++) {
                    float x = sv[cc];
                    float u = x * 0.02f;
                    float u2 = u * u;
                    // tanh poly (|u|<=0.35): err < 2e-6
                    float val = x * (1.f + u2 * (-0.333333333f +
                                  u2 * (0.133333333f + u2 * -0.053968254f)));
                    if (u2 > 0.1225f) val = 50.f * tanhf(u);
                    int kcol = k0 + tx * 4 + cc;
                    if (kcol > qrow) val = -1.0e30f;
                    sv[cc] = val;
                }
                float mx = fmaxf(fmaxf(sv[0], sv[1]), fmaxf(sv[2], sv[3]));
#pragma unroll
                for (int off = 1; off < 16; off <<= 1)
                    mx = fmaxf(mx, __shfl_xor_sync(0xffffffffu, mx, off));
                float mn = fmaxf(m[r], mx);
                float rescale = exp2f((m[r] - mn) * LOG2E);
                float psum = 0.f;
                float4 pw;
                pw.x = to_tf32(exp2f((sv[0] - mn) * LOG2E));
                pw.y = to_tf32(exp2f((sv[1] - mn) * LOG2E));
                pw.z = to_tf32(exp2f((sv[2] - mn) * LOG2E));
                pw.w = to_tf32(exp2f((sv[3] - mn) * LOG2E));
                psum = (pw.x + pw.y) + (pw.z + pw.w);
                *(float4*)&Ss[row * S_STRIDE + tx * 4] = pw;
#pragma unroll
                for (int off = 1; off < 16; off <<= 1)
                    psum += __shfl_xor_sync(0xffffffffu, psum, off);
                l[r] = l[r] * rescale + psum;
                m[r] = mn;
                if (tx == 0) rs[row] = rescale;
            }
            __syncthreads();

            // ---- rescale O frags, then PV ----
            float rc0 = rs[r0], rc1 = rs[r0 + 8];
#pragma unroll
            for (int nt = 0; nt < 16; nt++) {
                o[nt][0] *= rc0; o[nt][1] *= rc0;
                o[nt][2] *= rc1; o[nt][3] *= rc1;
            }
#pragma unroll
            for (int ks = 0; ks < 8; ks++) {
                const int kc = ks * 8 + qd;
                uint32_t a[4];
                a[0] = Ssu[r0 * S_STRIDE + kc];
                a[1] = Ssu[(r0 + 8) * S_STRIDE + kc];
                a[2] = Ssu[r0 * S_STRIDE + kc + 4];
                a[3] = Ssu[(r0 + 8) * S_STRIDE + kc + 4];
#pragma unroll
                for (int nt = 0; nt < 16; nt++) {
                    int nc = wc * 128 + nt * 8 + grp;
                    uint32_t b0 = Vsu[kc * V_STRIDE + nc];
                    uint32_t b1 = Vsu[(kc + 4) * V_STRIDE + nc];
                    MMA_TF32(o[nt], a, b0, b1);
                }
            }
        }

        // ---- epilogue ----
        if (tx == 0) {
#pragma unroll
            for (int r = 0; r < 4; r++) li[ty * 4 + r] = 1.f / l[r];
        }
        __syncthreads();
        float li0 = li[r0], li1 = li[r0 + 8];
#pragma unroll
        for (int nt = 0; nt < 16; nt++) {
            int col = h * HD + wc * 128 + nt * 8 + 2 * qd;
            *(float2*)&g_attn[(size_t)(q0 + r0) * (NH * HD) + col] =
                make_float2(to_tf32(o[nt][0] * li0), to_tf32(o[nt][1] * li0));
            *(float2*)&g_attn[(size_t)(q0 + r0 + 8) * (NH * HD) + col] =
                make_float2(to_tf32(o[nt][2] * li1), to_tf32(o[nt][3] * li1));
        }
    }
}

// ---------------------------------------------------------------------------
extern "C" void kernel_launch(void* const* d_in, const int* in_sizes, int n_in,
                              void* d_out, int out_size)
{
    const float* hs  = (const float*)d_in[0];
    // d_in[1] = attention_mask: pure causal (window >= S), recomputed in-kernel
    const void*  pos = d_in[2];
    const float* wq  = (const float*)d_in[3];
    const float* wk  = (const float*)d_in[4];
    const float* wv  = (const float*)d_in[5];
    const float* wo  = (const float*)d_in[6];
    float* out = (float*)d_out;

    float *pq, *pk, *pv, *pa, *phs, *pwq, *pwk, *pwv, *pwo;
    cudaGetSymbolAddress((void**)&pq,  g_q);
    cudaGetSymbolAddress((void**)&pk,  g_k);
    cudaGetSymbolAddress((void**)&pv,  g_v);
    cudaGetSymbolAddress((void**)&pa,  g_attn);
    cudaGetSymbolAddress((void**)&phs, g_hs_r);
    cudaGetSymbolAddress((void**)&pwq, g_wq_r);
    cudaGetSymbolAddress((void**)&pwk, g_wk_r);
    cudaGetSymbolAddress((void**)&pwv, g_wv_r);
    cudaGetSymbolAddress((void**)&pwo, g_wo_r);

    auto roundN = [&](const float* in, float* o, size_t n) {
        int n4 = (int)(n / 4);
        round_tf32_kernel<<<(n4 + 255) / 256, 256>>>(in, o, n4);
    };
    roundN(hs, phs, (size_t)S_LEN * HIDDEN);
    roundN(wq, pwq, (size_t)HIDDEN * 2048);
    roundN(wk, pwk, (size_t)HIDDEN * 1024);
    roundN(wv, pwv, (size_t)HIDDEN * 1024);
    roundN(wo, pwo, (size_t)2048 * HIDDEN);

    dim3 blk(256);
    tf32_gemm_kernel<<<dim3(2048 / 128, S_LEN / 128), blk>>>(phs, pwq, nullptr, pq,
                                                             S_LEN, 2048, HIDDEN, 1);
    tf32_gemm_kernel<<<dim3(1024 / 128, S_LEN / 128), blk>>>(phs, pwk, nullptr, pk,
                                                             S_LEN, 1024, HIDDEN, 1);
    tf32_gemm_kernel<<<dim3(1024 / 128, S_LEN / 128), blk>>>(phs, pwv, nullptr, pv,
                                                             S_LEN, 1024, HIDDEN, 1);
    rope_kernel<<<(S_LEN * 128) / 256, 256>>>(pos);

    const int attn_smem = ATTN_SMEM_FLOATS * 4;   // 222,720 B
    cudaFuncSetAttribute(attn_mma_kernel,
                         cudaFuncAttributeMaxDynamicSharedMemorySize, attn_smem);
    attn_mma_kernel<<<dim3(32, NH), blk, attn_smem>>>();

    tf32_gemm_kernel<<<dim3(2048 / 128, S_LEN / 128), blk>>>(pa, pwo, out, nullptr,
                                                             S_LEN, HIDDEN, 2048, 0);
}

// round 7
// speedup vs baseline: 4.7062x; 1.1334x over previous
#include <cuda_runtime.h>
#include <cuda_bf16.h>
#include <math.h>
#include <stdint.h>

#define S_LEN 4096
#define HIDDEN 2048
#define NH 8
#define NKV 4
#define HD 256

// ---------------- scratch (allocation-free device globals) -----------------
__device__ float g_q[(size_t)NH * S_LEN * HD];      // [h][s][d], tf32-rounded
__device__ float g_k[(size_t)NKV * S_LEN * HD];     // [h][s][d], tf32-rounded
__device__ float g_v[(size_t)NKV * S_LEN * HD];     // [h][s][d], tf32-rounded
__device__ float g_attn[(size_t)S_LEN * (NH * HD)]; // [s][h*HD+d], tf32-rounded
__device__ float g_hs_r[(size_t)S_LEN * HIDDEN];
__device__ float g_wq_r[(size_t)HIDDEN * (NH * HD)];
__device__ float g_wk_r[(size_t)HIDDEN * (NKV * HD)];
__device__ float g_wv_r[(size_t)HIDDEN * (NKV * HD)];
__device__ float g_wo_r[(size_t)(NH * HD) * HIDDEN];

__device__ __forceinline__ float to_tf32(float x) {
    float r;
    asm("cvt.rna.tf32.f32 %0, %1;" : "=f"(r) : "f"(x));
    return r;
}

__device__ __forceinline__ uint32_t cvta_shared(const void* p) {
    uint32_t a;
    asm("{ .reg .u64 t; cvta.to.shared.u64 t, %1; cvt.u32.u64 %0, t; }"
        : "=r"(a) : "l"(p));
    return a;
}

__device__ __forceinline__ void cp16(uint32_t dst, const void* src) {
    asm volatile("cp.async.cg.shared.global [%0], [%1], 16;"
                 :: "r"(dst), "l"(src));
}
#define CP_COMMIT() asm volatile("cp.async.commit_group;")
#define CP_WAIT0()  asm volatile("cp.async.wait_group 0;")
#define CP_WAIT1()  asm volatile("cp.async.wait_group 1;")

#define MMA_TF32(C, A, B0, B1)                                              \
    asm volatile(                                                           \
        "mma.sync.aligned.m16n8k8.row.col.f32.tf32.tf32.f32 "               \
        "{%0,%1,%2,%3}, {%4,%5,%6,%7}, {%8,%9}, {%0,%1,%2,%3};"             \
        : "+f"((C)[0]), "+f"((C)[1]), "+f"((C)[2]), "+f"((C)[3])            \
        : "r"((A)[0]), "r"((A)[1]), "r"((A)[2]), "r"((A)[3]),               \
          "r"(B0), "r"(B1))

// ---------------------------------------------------------------------------
// Prepass: round fp32 -> tf32-in-fp32 (rna), vectorized.
// ---------------------------------------------------------------------------
__global__ void round_tf32_kernel(const float* __restrict__ in,
                                  float* __restrict__ out, int n4)
{
    int i = blockIdx.x * blockDim.x + threadIdx.x;
    if (i >= n4) return;
    float4 v = ((const float4*)in)[i];
    v.x = to_tf32(v.x); v.y = to_tf32(v.y);
    v.z = to_tf32(v.z); v.w = to_tf32(v.w);
    ((float4*)out)[i] = v;
}

// ---------------------------------------------------------------------------
// Pipelined tf32 GEMM (cp.async double-buffered), C = A[M,2048] @ B[2048,N].
// 128x128 tile, BK=32, 8 warps (4m x 2n), m16n8k8.
// merged=1: fused QKV projection. Global n selects region/weight/output:
//   n <  2048       -> wq -> g_q head n>>8
//   2048 <= n <3072 -> wk -> g_k head (n-2048)>>8
//   n >= 3072       -> wv -> g_v head (n-3072)>>8
//   headed layouts written tf32-rounded.
// merged=0: B = B0 (N=2048), plain fp32 C to Cplain.
// ---------------------------------------------------------------------------
#define GP_BS    (128 * 36)               // B tile offset in floats
#define GP_STAGE (128 * 36 + 32 * 136)    // 8960 floats per stage
#define GP_SMEM  (2 * GP_STAGE * 4)       // 71680 B

__global__ __launch_bounds__(256, 2) void gemm_pipe_kernel(
    const float* __restrict__ A,
    const float* __restrict__ B0, const float* __restrict__ B1,
    const float* __restrict__ B2,
    float* __restrict__ Cq, float* __restrict__ Ck, float* __restrict__ Cv,
    float* __restrict__ Cplain, int M, int merged)
{
    extern __shared__ float gsm[];
    const uint32_t smem_base = cvta_shared(gsm);

    const int tid  = threadIdx.x;
    const int lane = tid & 31;
    const int wid  = tid >> 5;
    const int wm   = (wid & 3) * 32;
    const int wn   = (wid >> 2) * 64;
    const int bm   = blockIdx.y * 128;
    const int bn   = blockIdx.x * 128;
    const int grp  = lane >> 2;
    const int qd   = lane & 3;

    // region select
    const float* Bp;
    float* Cp = Cplain;
    int nb, Nr, head = 0, colb = 0;
    if (merged) {
        if (bn < 2048)      { Bp = B0; Cp = Cq; nb = bn;        Nr = 2048; }
        else if (bn < 3072) { Bp = B1; Cp = Ck; nb = bn - 2048; Nr = 1024; }
        else                { Bp = B2; Cp = Cv; nb = bn - 3072; Nr = 1024; }
        head = nb >> 8;
        colb = nb & 255;
    } else {
        Bp = B0; nb = bn; Nr = 2048;
    }

    // per-thread staging coords
    const int a_r  = tid >> 3, a_c4 = tid & 7;    // + p*32 rows
    const int b_r  = tid >> 5, b_c4 = tid & 31;   // + p*8 rows

    auto load_stage = [&](int chunk, int st) {
        const int k0 = chunk * 32;
        const uint32_t ab = smem_base + st * (GP_STAGE * 4);
        const uint32_t bb = ab + GP_BS * 4;
#pragma unroll
        for (int p = 0; p < 4; p++) {
            int r = a_r + p * 32;
            cp16(ab + r * 144 + a_c4 * 16,
                 &A[(size_t)(bm + r) * 2048 + k0 + a_c4 * 4]);
        }
#pragma unroll
        for (int p = 0; p < 4; p++) {
            int r = b_r + p * 8;
            cp16(bb + r * 544 + b_c4 * 16,
                 &Bp[(size_t)(k0 + r) * Nr + nb + b_c4 * 4]);
        }
        CP_COMMIT();
    };

    float c[2][8][4];
#pragma unroll
    for (int mt = 0; mt < 2; mt++)
#pragma unroll
        for (int nt = 0; nt < 8; nt++)
#pragma unroll
            for (int r = 0; r < 4; r++) c[mt][nt][r] = 0.f;

    load_stage(0, 0);

    for (int i = 0; i < 64; i++) {
        const int st = i & 1;
        CP_WAIT0();
        __syncthreads();
        if (i + 1 < 64) load_stage(i + 1, st ^ 1);

        const uint32_t* Asu = (const uint32_t*)(gsm + st * GP_STAGE);
        const uint32_t* Bsu = Asu + GP_BS;
#pragma unroll
        for (int ks = 0; ks < 4; ks++) {
            const int kc = ks * 8 + qd;
            uint32_t a[2][4];
#pragma unroll
            for (int mt = 0; mt < 2; mt++) {
                int r0 = wm + mt * 16 + grp;
                a[mt][0] = Asu[r0 * 36 + kc];
                a[mt][1] = Asu[(r0 + 8) * 36 + kc];
                a[mt][2] = Asu[r0 * 36 + kc + 4];
                a[mt][3] = Asu[(r0 + 8) * 36 + kc + 4];
            }
#pragma unroll
            for (int nt = 0; nt < 8; nt++) {
                int nc = wn + nt * 8 + grp;
                uint32_t b0 = Bsu[kc * 136 + nc];
                uint32_t b1 = Bsu[(kc + 4) * 136 + nc];
#pragma unroll
                for (int mt = 0; mt < 2; mt++)
                    MMA_TF32(c[mt][nt], a[mt], b0, b1);
            }
        }
        __syncthreads();
    }

    const int m0 = bm + wm + grp;
    const int n0 = wn + 2 * qd;    // local col 0..127
    if (merged) {
        const size_t hbase = (size_t)head * ((size_t)M * HD) + colb;
#pragma unroll
        for (int mt = 0; mt < 2; mt++)
#pragma unroll
            for (int nt = 0; nt < 8; nt++) {
                int m = m0 + mt * 16;
                int ncol = n0 + nt * 8;
                *(float2*)&Cp[hbase + (size_t)m * HD + ncol] =
                    make_float2(to_tf32(c[mt][nt][0]), to_tf32(c[mt][nt][1]));
                *(float2*)&Cp[hbase + (size_t)(m + 8) * HD + ncol] =
                    make_float2(to_tf32(c[mt][nt][2]), to_tf32(c[mt][nt][3]));
            }
    } else {
#pragma unroll
        for (int mt = 0; mt < 2; mt++)
#pragma unroll
            for (int nt = 0; nt < 8; nt++) {
                int m = m0 + mt * 16;
                int n = bn + n0 + nt * 8;
                *(float2*)&Cplain[(size_t)m * 2048 + n] =
                    make_float2(c[mt][nt][0], c[mt][nt][1]);
                *(float2*)&Cplain[(size_t)(m + 8) * 2048 + n] =
                    make_float2(c[mt][nt][2], c[mt][nt][3]);
            }
    }
}

// ---------------------------------------------------------------------------
// RoPE: one thread per (s, i); cos/sin once (fp64 range reduction), applied
// to all 12 heads. Folds SCALING=0.0625 into q. tf32-rounds outputs.
// position_ids int32/int64 auto-detected via word[1].
// ---------------------------------------------------------------------------
__global__ void rope_kernel(const void* __restrict__ pos_raw)
{
    int idx = blockIdx.x * blockDim.x + threadIdx.x;
    if (idx >= S_LEN * 128) return;
    int i = idx & 127;
    int s = idx >> 7;

    const int* p32 = (const int*)pos_raw;
    long long pll = (p32[1] == 0) ? ((const long long*)pos_raw)[s]
                                  : (long long)p32[s];
    float p = (float)pll;

    double invd = exp(-(double)i * (9.210340371976184 / 128.0));
    float f = (float)((double)p * invd);
    const double TWO_PI = 6.283185307179586476925287;
    double r = (double)f;
    r -= TWO_PI * floor(r / TWO_PI);
    float sv = sinf((float)r);
    float cv = cosf((float)r);

#pragma unroll
    for (int h = 0; h < NH; h++) {
        float* base = g_q + ((size_t)h * S_LEN + s) * HD;
        float x1 = base[i], x2 = base[i + 128];
        base[i]       = to_tf32((x1 * cv - x2 * sv) * 0.0625f);
        base[i + 128] = to_tf32((x2 * cv + x1 * sv) * 0.0625f);
    }
#pragma unroll
    for (int h = 0; h < NKV; h++) {
        float* base = g_k + ((size_t)h * S_LEN + s) * HD;
        float x1 = base[i], x2 = base[i + 128];
        base[i]       = to_tf32(x1 * cv - x2 * sv);
        base[i + 128] = to_tf32(x2 * cv + x1 * sv);
    }
}

// ---------------------------------------------------------------------------
// Tensor-core flash attention (tf32 mma.sync) with tanh softcap.
// Block = (head, q-tile pair): q-tiles bx and 63-bx -> 65 k-blocks, uniform.
// K staged via cp.async (group 0), V via cp.async (group 1) so the V load
// overlaps the QK MMAs. Softmax SIMT with online max/sum.
// ---------------------------------------------------------------------------
#define QK_STRIDE 268
#define V_STRIDE  264
#define S_STRIDE  68
#define OFF_QF 0
#define OFF_KF (64 * QK_STRIDE)
#define OFF_SS (OFF_KF + 64 * QK_STRIDE)
#define OFF_VS (OFF_SS + 64 * S_STRIDE)
#define OFF_RS (OFF_VS + 64 * V_STRIDE)
#define OFF_LI (OFF_RS + 64)
#define ATTN_SMEM_FLOATS (OFF_LI + 64)

__global__ __launch_bounds__(256) void attn_mma_kernel()
{
    extern __shared__ float sm[];
    float* Qf = sm + OFF_QF;
    float* Ss = sm + OFF_SS;
    float* rs = sm + OFF_RS;
    float* li = sm + OFF_LI;
    const uint32_t* Qfu = (const uint32_t*)Qf;
    const uint32_t* Kfu = (const uint32_t*)(sm + OFF_KF);
    const uint32_t* Ssu = (const uint32_t*)Ss;
    const uint32_t* Vsu = (const uint32_t*)(sm + OFF_VS);
    const uint32_t smem_base = cvta_shared(sm);
    const uint32_t kf_base = smem_base + OFF_KF * 4;
    const uint32_t vs_base = smem_base + OFF_VS * 4;

    const int h  = blockIdx.y;
    const int hk = h >> 1;
    const int tid  = threadIdx.x;
    const int lane = tid & 31;
    const int wid  = tid >> 5;
    const int wr   = wid & 3;
    const int wc   = wid >> 2;
    const int grp  = lane >> 2;
    const int qd   = lane & 3;
    const int r0   = wr * 16 + grp;
    const int ty   = tid >> 4;
    const int tx   = tid & 15;

    const float* Qh = g_q + (size_t)h  * S_LEN * HD;
    const float* Kh = g_k + (size_t)hk * S_LEN * HD;
    const float* Vh = g_v + (size_t)hk * S_LEN * HD;

    const float LOG2E = 1.4426950408889634f;
    const int lrow = tid >> 2;          // 0..63 (4 float4 per row slot)
    const int lc4  = (tid & 3);         // 0..3 -> 16 float4 per row total

    for (int half = 0; half < 2; half++) {
        const int qt = half ? (63 - blockIdx.x) : blockIdx.x;
        const int q0 = qt * 64;

        __syncthreads();
#pragma unroll
        for (int p = 0; p < 16; p++) {
            int idx = tid + p * 256;
            int row = idx >> 6, c4 = idx & 63;
            *(float4*)&Qf[row * QK_STRIDE + c4 * 4] =
                *(const float4*)&Qh[(size_t)(q0 + row) * HD + c4 * 4];
        }

        float m[4], l[4], o[16][4];
#pragma unroll
        for (int r = 0; r < 4; r++) { m[r] = -3.0e38f; l[r] = 0.f; }
#pragma unroll
        for (int nt = 0; nt < 16; nt++)
#pragma unroll
            for (int r = 0; r < 4; r++) o[nt][r] = 0.f;

        for (int kb = 0; kb <= qt; kb++) {
            const int k0 = kb * 64;
            __syncthreads();   // prior QK/PV reads of Kf/Vs complete
            // K tile (group committed first -> waited by CP_WAIT1)
#pragma unroll
            for (int p = 0; p < 16; p++) {
                int idx = tid + p * 256;
                int row = idx >> 6, c4 = idx & 63;
                cp16(kf_base + row * (QK_STRIDE * 4) + c4 * 16,
                     &Kh[(size_t)(k0 + row) * HD + c4 * 4]);
            }
            CP_COMMIT();
            // V tile (overlaps QK MMAs below)
#pragma unroll
            for (int p = 0; p < 16; p++) {
                int idx = tid + p * 256;
                int row = idx >> 6, c4 = idx & 63;
                cp16(vs_base + row * (V_STRIDE * 4) + c4 * 16,
                     &Vh[(size_t)(k0 + row) * HD + c4 * 4]);
            }
            CP_COMMIT();
            CP_WAIT1();        // K ready (V may still be in flight)
            __syncthreads();

            // ---- QK: S[64][64] fragments ----
            float s[4][4];
#pragma unroll
            for (int nt = 0; nt < 4; nt++)
#pragma unroll
                for (int r = 0; r < 4; r++) s[nt][r] = 0.f;
#pragma unroll 8
            for (int ks = 0; ks < 32; ks++) {
                const int kc = ks * 8 + qd;
                uint32_t a[4];
                a[0] = Qfu[r0 * QK_STRIDE + kc];
                a[1] = Qfu[(r0 + 8) * QK_STRIDE + kc];
                a[2] = Qfu[r0 * QK_STRIDE + kc + 4];
                a[3] = Qfu[(r0 + 8) * QK_STRIDE + kc + 4];
#pragma unroll
                for (int nt = 0; nt < 4; nt++) {
                    int nc = wc * 32 + nt * 8 + grp;
                    uint32_t b0 = Kfu[nc * QK_STRIDE + kc];
                    uint32_t b1 = Kfu[nc * QK_STRIDE + kc + 4];
                    MMA_TF32(s[nt], a, b0, b1);
                }
            }
#pragma unroll
            for (int nt = 0; nt < 4; nt++) {
                int col = wc * 32 + nt * 8 + 2 * qd;
                *(float2*)&Ss[r0 * S_STRIDE + col] = make_float2(s[nt][0], s[nt][1]);
                *(float2*)&Ss[(r0 + 8) * S_STRIDE + col] = make_float2(s[nt][2], s[nt][3]);
            }
            CP_WAIT0();        // V ready
            __syncthreads();   // publish Ss (and V)

            // ---- softcap + causal + online softmax (SIMT) ----
#pragma unroll
            for (int r = 0; r < 4; r++) {
                const int row = ty * 4 + r;
                const int qrow = q0 + row;
                float4 raw = *(float4*)&Ss[row * S_STRIDE + tx * 4];
                float sv[4] = {raw.x, raw.y, raw.z, raw.w};
#pragma unroll
                for (int cc = 0; cc < 4; cc++) {
                    float x = sv[cc];
                    float u = x * 0.02f;
                    float u2 = u * u;
                    float val = x * (1.f + u2 * (-0.333333333f +
                                  u2 * (0.133333333f + u2 * -0.053968254f)));
                    if (u2 > 0.1225f) val = 50.f * tanhf(u);
                    int kcol = k0 + tx * 4 + cc;
                    if (kcol > qrow) val = -1.0e30f;
                    sv[cc] = val;
                }
                float mx = fmaxf(fmaxf(sv[0], sv[1]), fmaxf(sv[2], sv[3]));
#pragma unroll
                for (int off = 1; off < 16; off <<= 1)
                    mx = fmaxf(mx, __shfl_xor_sync(0xffffffffu, mx, off));
                float mn = fmaxf(m[r], mx);
                float rescale = exp2f((m[r] - mn) * LOG2E);
                float4 pw;
                pw.x = to_tf32(exp2f((sv[0] - mn) * LOG2E));
                pw.y = to_tf32(exp2f((sv[1] - mn) * LOG2E));
                pw.z = to_tf32(exp2f((sv[2] - mn) * LOG2E));
                pw.w = to_tf32(exp2f((sv[3] - mn) * LOG2E));
                float psum = (pw.x + pw.y) + (pw.z + pw.w);
                *(float4*)&Ss[row * S_STRIDE + tx * 4] = pw;
#pragma unroll
                for (int off = 1; off < 16; off <<= 1)
                    psum += __shfl_xor_sync(0xffffffffu, psum, off);
                l[r] = l[r] * rescale + psum;
                m[r] = mn;
                if (tx == 0) rs[row] = rescale;
            }
            __syncthreads();

            // ---- rescale O frags, then PV ----
            float rc0 = rs[r0], rc1 = rs[r0 + 8];
#pragma unroll
            for (int nt = 0; nt < 16; nt++) {
                o[nt][0] *= rc0; o[nt][1] *= rc0;
                o[nt][2] *= rc1; o[nt][3] *= rc1;
            }
#pragma unroll
            for (int ks = 0; ks < 8; ks++) {
                const int kc = ks * 8 + qd;
                uint32_t a[4];
                a[0] = Ssu[r0 * S_STRIDE + kc];
                a[1] = Ssu[(r0 + 8) * S_STRIDE + kc];
                a[2] = Ssu[r0 * S_STRIDE + kc + 4];
                a[3] = Ssu[(r0 + 8) * S_STRIDE + kc + 4];
#pragma unroll
                for (int nt = 0; nt < 16; nt++) {
                    int nc = wc * 128 + nt * 8 + grp;
                    uint32_t b0 = Vsu[kc * V_STRIDE + nc];
                    uint32_t b1 = Vsu[(kc + 4) * V_STRIDE + nc];
                    MMA_TF32(o[nt], a, b0, b1);
                }
            }
        }

        // ---- epilogue: normalize, tf32-round, write [s][h*HD+d] ----
        if (tx == 0) {
#pragma unroll
            for (int r = 0; r < 4; r++) li[ty * 4 + r] = 1.f / l[r];
        }
        __syncthreads();
        float li0 = li[r0], li1 = li[r0 + 8];
#pragma unroll
        for (int nt = 0; nt < 16; nt++) {
            int col = h * HD + wc * 128 + nt * 8 + 2 * qd;
            *(float2*)&g_attn[(size_t)(q0 + r0) * (NH * HD) + col] =
                make_float2(to_tf32(o[nt][0] * li0), to_tf32(o[nt][1] * li0));
            *(float2*)&g_attn[(size_t)(q0 + r0 + 8) * (NH * HD) + col] =
                make_float2(to_tf32(o[nt][2] * li1), to_tf32(o[nt][3] * li1));
        }
    }
}

// ---------------------------------------------------------------------------
extern "C" void kernel_launch(void* const* d_in, const int* in_sizes, int n_in,
                              void* d_out, int out_size)
{
    const float* hs  = (const float*)d_in[0];
    // d_in[1] = attention_mask: pure causal (window >= S), recomputed in-kernel
    const void*  pos = d_in[2];
    const float* wq  = (const float*)d_in[3];
    const float* wk  = (const float*)d_in[4];
    const float* wv  = (const float*)d_in[5];
    const float* wo  = (const float*)d_in[6];
    float* out = (float*)d_out;

    float *pq, *pk, *pv, *pa, *phs, *pwq, *pwk, *pwv, *pwo;
    cudaGetSymbolAddress((void**)&pq,  g_q);
    cudaGetSymbolAddress((void**)&pk,  g_k);
    cudaGetSymbolAddress((void**)&pv,  g_v);
    cudaGetSymbolAddress((void**)&pa,  g_attn);
    cudaGetSymbolAddress((void**)&phs, g_hs_r);
    cudaGetSymbolAddress((void**)&pwq, g_wq_r);
    cudaGetSymbolAddress((void**)&pwk, g_wk_r);
    cudaGetSymbolAddress((void**)&pwv, g_wv_r);
    cudaGetSymbolAddress((void**)&pwo, g_wo_r);

    cudaFuncSetAttribute(gemm_pipe_kernel,
                         cudaFuncAttributeMaxDynamicSharedMemorySize, GP_SMEM);
    const int attn_smem = ATTN_SMEM_FLOATS * 4;
    cudaFuncSetAttribute(attn_mma_kernel,
                         cudaFuncAttributeMaxDynamicSharedMemorySize, attn_smem);

    auto roundN = [&](const float* in, float* o, size_t n) {
        int n4 = (int)(n / 4);
        round_tf32_kernel<<<(n4 + 255) / 256, 256>>>(in, o, n4);
    };
    roundN(hs, phs, (size_t)S_LEN * HIDDEN);
    roundN(wq, pwq, (size_t)HIDDEN * 2048);
    roundN(wk, pwk, (size_t)HIDDEN * 1024);
    roundN(wv, pwv, (size_t)HIDDEN * 1024);
    roundN(wo, pwo, (size_t)2048 * HIDDEN);

    // Fused QKV projection (one launch, N=4096)
    gemm_pipe_kernel<<<dim3(32, 32), 256, GP_SMEM>>>(
        phs, pwq, pwk, pwv, pq, pk, pv, nullptr, S_LEN, 1);
    // RoPE (+ fold attention scaling into q)
    rope_kernel<<<(S_LEN * 128) / 256, 256>>>(pos);
    // Causal flash attention with tanh softcap
    attn_mma_kernel<<<dim3(32, NH), 256, attn_smem>>>();
    // Output projection
    gemm_pipe_kernel<<<dim3(16, 32), 256, GP_SMEM>>>(
        pa, pwo, nullptr, nullptr, nullptr, nullptr, nullptr, out, S_LEN, 0);
}